// round 6
// baseline (speedup 1.0000x reference)
#include <cuda_runtime.h>

#define AALPHA 0.42f
#define IMG_H 1024
#define IMG_W 1024
#define NIMG 48     // 16 batches * 3 masks
#define RPB 64      // output rows per block
#define BPI 16      // blocks per image (IMG_H / RPB)

__device__ float g_part[NIMG * BPI];
__device__ float g_weights[NIMG];

// sigmoid(x) = 0.5*tanh(x/2)+0.5  (1 MUFU + 2 fma)
__device__ __forceinline__ float fsig(float x) {
    float t;
    asm("tanh.approx.f32 %0, %1;" : "=f"(t) : "f"(0.5f * x));
    return fmaf(0.5f, t, 0.5f);
}
__device__ __forceinline__ float fsqrt_fast(float x) {
    float r; asm("sqrt.approx.f32 %0, %1;" : "=f"(r) : "f"(x)); return r;
}

// ---------------------------------------------------------------------------
// score = ALPHA * sum(edge) + (1-ALPHA)/49 * sum( cnt(p) * (m_p - mean_p)^2 )
// BARRIER-FREE: each thread owns cols 4t..4t+3 and loads 3 overlapping
// float4 (c0-4, c0, c0+4; dedup in L1/L2), computing all 10 sigmoids it
// needs itself. No smem row exchange, no __syncthreads in the row loop ->
// warps fully independent. 1-row prefetch of all three loads.
// Interior blocks (1..14): fully static clean path. Blocks 0/15: guarded.
// ---------------------------------------------------------------------------
__global__ __launch_bounds__(256, 2) void score_kernel(const float* __restrict__ logits) {
    __shared__ float red[8];

    const int img = blockIdx.y;
    const int y0  = blockIdx.x * RPB;
    const int t   = threadIdx.x;
    const int c0  = t * 4;
    const float* base = logits + (size_t)img * (IMG_H * IMG_W);

    const bool lok = (t != 0);      // left float4 exists
    const bool rok = (t != 255);    // right float4 exists

    float hr[8][4];                      // horizontal-7-sum ring
    float rs[4][4], rt[4][4], rc[4][4];  // conv combo ring
    float vs[4] = {0.f, 0.f, 0.f, 0.f};
    #pragma unroll
    for (int k = 0; k < 8; ++k) { hr[k][0]=hr[k][1]=hr[k][2]=hr[k][3]=0.f; }
    #pragma unroll
    for (int k = 0; k < 4; ++k) {
        #pragma unroll
        for (int j = 0; j < 4; ++j) { rs[k][j]=0.f; rt[k][j]=0.f; rc[k][j]=0.f; }
    }

    float acc_e = 0.f, acc_v = 0.f, acc;

    if (blockIdx.x >= 1 && blockIdx.x <= 14) {
        // ================= clean path: all rows in-bounds, chf = 7 =========
        const bool inter = lok && rok;          // all 4 cols have cw = 7
        float cw4n[4];
        #pragma unroll
        for (int j = 0; j < 4; ++j) {
            int col = c0 + j;
            cw4n[j] = (float)(min(col, 3) + min(IMG_W - 1 - col, 3) + 1) * (1.0f / 7.0f);
        }

        const float* rp = base + (size_t)(y0 - 3) * IMG_W + c0;
        float4 cM = *(const float4*)rp;
        float4 cL = lok ? *(const float4*)(rp - 4) : make_float4(0.f,0.f,0.f,0.f);
        float4 cR = rok ? *(const float4*)(rp + 4) : make_float4(0.f,0.f,0.f,0.f);
        rp += IMG_W;

#define ROW_CLEAN(U, DOOUT, DOPREF)                                         \
    do {                                                                    \
        float4 nM, nL, nR;                                                  \
        if (DOPREF) {                                                       \
            nM = *(const float4*)rp;                                        \
            nL = lok ? *(const float4*)(rp - 4) : make_float4(0.f,0.f,0.f,0.f); \
            nR = rok ? *(const float4*)(rp + 4) : make_float4(0.f,0.f,0.f,0.f); \
            rp += IMG_W;                                                    \
        } else {                                                            \
            nM = make_float4(0.f,0.f,0.f,0.f); nL = nM; nR = nM;            \
        }                                                                   \
        float n0 = lok ? fsig(cL.y) : 0.f;                                  \
        float n1 = lok ? fsig(cL.z) : 0.f;                                  \
        float n2 = lok ? fsig(cL.w) : 0.f;                                  \
        float n3 = fsig(cM.x), n4 = fsig(cM.y);                             \
        float n5 = fsig(cM.z), n6 = fsig(cM.w);                             \
        float n7 = rok ? fsig(cR.x) : 0.f;                                  \
        float n8 = rok ? fsig(cR.y) : 0.f;                                  \
        float n9 = rok ? fsig(cR.z) : 0.f;                                  \
        float h0 = ((n0 + n1) + (n2 + n3)) + ((n4 + n5) + n6);              \
        float h1 = h0 + n7 - n0;                                            \
        float h2 = h1 + n8 - n1;                                            \
        float h3 = h2 + n9 - n2;                                            \
        vs[0] += h0 - hr[((U) + 1) & 7][0];                                 \
        vs[1] += h1 - hr[((U) + 1) & 7][1];                                 \
        vs[2] += h2 - hr[((U) + 1) & 7][2];                                 \
        vs[3] += h3 - hr[((U) + 1) & 7][3];                                 \
        hr[(U) & 7][0] = h0; hr[(U) & 7][1] = h1;                           \
        hr[(U) & 7][2] = h2; hr[(U) & 7][3] = h3;                           \
        if (DOOUT) {                                                        \
            const int T = (U) & 3, M = ((U) + 1) & 3, Bo = ((U) + 2) & 3;   \
            float rowv = 0.f;                                               \
            _Pragma("unroll")                                               \
            for (int j = 0; j < 4; ++j) {                                   \
                float gxv = fmaf(2.f, rt[M][j], rt[T][j] + rt[Bo][j]);      \
                float gyv = rs[T][j] - rs[Bo][j];                           \
                float lap = fmaf(-6.f, rc[M][j],                            \
                                 (rc[T][j] + rc[Bo][j]) + rs[M][j]);        \
                acc_e += fsqrt_fast(fmaf(gxv, gxv, gyv * gyv))              \
                         + 0.5f * fabsf(lap);                               \
                float d = fmaf(-(1.f / 49.f), vs[j], rc[M][j]);             \
                if (inter) rowv = fmaf(d, d, rowv);                         \
                else       rowv = fmaf(d * cw4n[j], d, rowv);               \
            }                                                               \
            acc_v += rowv;                                                  \
        }                                                                   \
        const int W = (U) & 3;                                              \
        rs[W][0] = fmaf(2.f, n3, n2 + n4); rt[W][0] = n2 - n4; rc[W][0] = n3; \
        rs[W][1] = fmaf(2.f, n4, n3 + n5); rt[W][1] = n3 - n5; rc[W][1] = n4; \
        rs[W][2] = fmaf(2.f, n5, n4 + n6); rt[W][2] = n4 - n6; rc[W][2] = n5; \
        rs[W][3] = fmaf(2.f, n6, n5 + n7); rt[W][3] = n5 - n7; rc[W][3] = n6; \
        cM = nM; cL = nL; cR = nR;                                          \
    } while (0)

        // prologue rows 0..7 (output only rows 6,7)
        ROW_CLEAN(0, false, true); ROW_CLEAN(1, false, true);
        ROW_CLEAN(2, false, true); ROW_CLEAN(3, false, true);
        ROW_CLEAN(4, false, true); ROW_CLEAN(5, false, true);
        ROW_CLEAN(6, true,  true); ROW_CLEAN(7, true,  true);

        // middle rows 8..63
        for (int ii = 8; ii < 64; ii += 8) {
            ROW_CLEAN(0, true, true); ROW_CLEAN(1, true, true);
            ROW_CLEAN(2, true, true); ROW_CLEAN(3, true, true);
            ROW_CLEAN(4, true, true); ROW_CLEAN(5, true, true);
            ROW_CLEAN(6, true, true); ROW_CLEAN(7, true, true);
        }

        // tail rows 64..69 (last prefetch at row 68)
        ROW_CLEAN(0, true, true); ROW_CLEAN(1, true, true);
        ROW_CLEAN(2, true, true); ROW_CLEAN(3, true, true);
        ROW_CLEAN(4, true, true); ROW_CLEAN(5, true, false);
#undef ROW_CLEAN

        acc = AALPHA * acc_e + ((1.0f - AALPHA) / 49.0f) * 7.0f * acc_v;
    } else {
        // ================= guarded path (blocks 0 and 15) ==================
        float cwf[4];
        #pragma unroll
        for (int j = 0; j < 4; ++j) {
            int col = c0 + j;
            cwf[j] = (float)(min(col, 3) + min(IMG_W - 1 - col, 3) + 1);
        }

        float4 z4 = make_float4(0.f, 0.f, 0.f, 0.f);
        float4 cM = z4, cL = z4, cR = z4;
        {
            int gy = y0 - 3;
            if ((unsigned)gy < IMG_H) {
                const float* r_ = base + (size_t)gy * IMG_W + c0;
                cM = *(const float4*)r_;
                if (lok) cL = *(const float4*)(r_ - 4);
                if (rok) cR = *(const float4*)(r_ + 4);
            }
        }

        for (int ii = 0; ii < 72; ii += 8) {
            #pragma unroll
            for (int u = 0; u < 8; ++u) {
                const int i  = ii + u;
                const int gy = y0 - 3 + i;
                const bool valid = ((unsigned)gy < IMG_H) && (i < 70);

                float4 nM = z4, nL = z4, nR = z4;
                {
                    int gyn = gy + 1;
                    if ((unsigned)gyn < IMG_H && (i + 1) < 70) {
                        const float* r_ = base + (size_t)gyn * IMG_W + c0;
                        nM = *(const float4*)r_;
                        if (lok) nL = *(const float4*)(r_ - 4);
                        if (rok) nR = *(const float4*)(r_ + 4);
                    }
                }

                const bool vl = valid && lok, vr = valid && rok;
                float n0 = vl ? fsig(cL.y) : 0.f;
                float n1 = vl ? fsig(cL.z) : 0.f;
                float n2 = vl ? fsig(cL.w) : 0.f;
                float n3 = valid ? fsig(cM.x) : 0.f;
                float n4 = valid ? fsig(cM.y) : 0.f;
                float n5 = valid ? fsig(cM.z) : 0.f;
                float n6 = valid ? fsig(cM.w) : 0.f;
                float n7 = vr ? fsig(cR.x) : 0.f;
                float n8 = vr ? fsig(cR.y) : 0.f;
                float n9 = vr ? fsig(cR.z) : 0.f;

                float h0 = ((n0 + n1) + (n2 + n3)) + ((n4 + n5) + n6);
                float h1 = h0 + n7 - n0;
                float h2 = h1 + n8 - n1;
                float h3 = h2 + n9 - n2;

                vs[0] += h0 - hr[(u + 1) & 7][0];
                vs[1] += h1 - hr[(u + 1) & 7][1];
                vs[2] += h2 - hr[(u + 1) & 7][2];
                vs[3] += h3 - hr[(u + 1) & 7][3];
                hr[u][0] = h0; hr[u][1] = h1; hr[u][2] = h2; hr[u][3] = h3;

                if (i >= 6 && i < 70) {
                    const int yo = gy - 3;
                    const float chf = (float)(min(yo, 3) + min(IMG_H - 1 - yo, 3) + 1);
                    const int T = u & 3, M = (u + 1) & 3, Bo = (u + 2) & 3;
                    float rowv = 0.f;
                    #pragma unroll
                    for (int j = 0; j < 4; ++j) {
                        float gxv = fmaf(2.f, rt[M][j], rt[T][j] + rt[Bo][j]);
                        float gyv = rs[T][j] - rs[Bo][j];
                        float lap = fmaf(-6.f, rc[M][j], (rc[T][j] + rc[Bo][j]) + rs[M][j]);
                        acc_e += fsqrt_fast(fmaf(gxv, gxv, gyv * gyv)) + 0.5f * fabsf(lap);
                        float d = fmaf(-(1.f / 49.f), vs[j], rc[M][j]);
                        rowv = fmaf(d * cwf[j], d, rowv);
                    }
                    acc_v += chf * rowv;
                }

                const int W = u & 3;
                rs[W][0] = fmaf(2.f, n3, n2 + n4); rt[W][0] = n2 - n4; rc[W][0] = n3;
                rs[W][1] = fmaf(2.f, n4, n3 + n5); rt[W][1] = n3 - n5; rc[W][1] = n4;
                rs[W][2] = fmaf(2.f, n5, n4 + n6); rt[W][2] = n4 - n6; rc[W][2] = n5;
                rs[W][3] = fmaf(2.f, n6, n5 + n7); rt[W][3] = n5 - n7; rc[W][3] = n6;

                cM = nM; cL = nL; cR = nR;
            }
        }
        acc = AALPHA * acc_e + ((1.0f - AALPHA) / 49.0f) * acc_v;
    }

    // block reduction -> per-block partial
    #pragma unroll
    for (int off = 16; off; off >>= 1)
        acc += __shfl_down_sync(0xffffffffu, acc, off);
    if ((t & 31) == 0) red[t >> 5] = acc;
    __syncthreads();
    if (t < 8) {
        float v = red[t];
        #pragma unroll
        for (int off = 4; off; off >>= 1)
            v += __shfl_down_sync(0xffu, v, off);
        if (t == 0) g_part[img * BPI + blockIdx.x] = v;
    }
}

// ---------------------------------------------------------------------------
// reduce partials; weights[b,s] = 0.5*(score/(sum+1e-6) + softmax(lw)[s])
// ---------------------------------------------------------------------------
__global__ void weights_kernel(const float* __restrict__ lw) {
    __shared__ float ss[NIMG];
    __shared__ float soft[3];
    int tid = threadIdx.x;
    if (tid < NIMG) {
        float s = 0.f;
        #pragma unroll
        for (int k = 0; k < BPI; ++k) s += g_part[tid * BPI + k];
        ss[tid] = s;
    }
    if (tid == 0) {
        float a = lw[0], b = lw[1], c = lw[2];
        float m = fmaxf(a, fmaxf(b, c));
        float e0 = expf(a - m), e1 = expf(b - m), e2 = expf(c - m);
        float inv = 1.0f / (e0 + e1 + e2);
        soft[0] = e0 * inv; soft[1] = e1 * inv; soft[2] = e2 * inv;
    }
    __syncthreads();
    if (tid < NIMG) {
        int b = tid / 3;
        int s = tid - b * 3;
        float denom = ss[b * 3] + ss[b * 3 + 1] + ss[b * 3 + 2] + 1e-6f;
        g_weights[tid] = (ss[tid] / denom + soft[s]) * 0.5f;
    }
}

// ---------------------------------------------------------------------------
// fused[b,p] = sum_s logits[b,s,p] * w[b,s]   (float4 vectorized)
// ---------------------------------------------------------------------------
__global__ __launch_bounds__(256) void fuse_kernel(const float* __restrict__ logits,
                                                   float* __restrict__ out) {
    const int N = IMG_H * IMG_W;
    int b = blockIdx.y;
    int i = blockIdx.x * blockDim.x + threadIdx.x;   // over N/4
    float w0 = g_weights[b * 3 + 0];
    float w1 = g_weights[b * 3 + 1];
    float w2 = g_weights[b * 3 + 2];
    const float4* p0 = (const float4*)(logits + (size_t)(b * 3 + 0) * N);
    const float4* p1 = (const float4*)(logits + (size_t)(b * 3 + 1) * N);
    const float4* p2 = (const float4*)(logits + (size_t)(b * 3 + 2) * N);
    float4 a = p0[i], bb = p1[i], cc = p2[i];
    float4 o;
    o.x = a.x * w0 + bb.x * w1 + cc.x * w2;
    o.y = a.y * w0 + bb.y * w1 + cc.y * w2;
    o.z = a.z * w0 + bb.z * w1 + cc.z * w2;
    o.w = a.w * w0 + bb.w * w1 + cc.w * w2;
    ((float4*)out)[(size_t)b * (N / 4) + i] = o;
}

extern "C" void kernel_launch(void* const* d_in, const int* in_sizes, int n_in,
                              void* d_out, int out_size) {
    const float* logits = (const float*)d_in[0];   // (16,3,1024,1024) fp32
    const float* lw     = (const float*)d_in[1];   // (3,) fp32
    float* out          = (float*)d_out;           // (16,1024,1024) fp32

    score_kernel<<<dim3(BPI, NIMG), 256>>>(logits);
    weights_kernel<<<1, 64>>>(lw);
    fuse_kernel<<<dim3((IMG_H * IMG_W / 4) / 256, 16), 256>>>(logits, out);
}

// round 7
// speedup vs baseline: 1.4693x; 1.4693x over previous
#include <cuda_runtime.h>

#define AALPHA 0.42f
#define IMG_H 1024
#define IMG_W 1024
#define NIMG 48     // 16 batches * 3 masks
#define RPB 64      // output rows per block
#define BPI 16      // blocks per image (IMG_H / RPB)

typedef unsigned long long u64;

__device__ float g_part[NIMG * BPI];
__device__ float g_weights[NIMG];

// ---- f32x2 helpers (SASS FFMA2/FADD2/FMUL2, PTX-only path) ----------------
__device__ __forceinline__ u64 pk2(float a, float b) {
    u64 r; asm("mov.b64 %0, {%1, %2};" : "=l"(r) : "f"(a), "f"(b)); return r;
}
__device__ __forceinline__ void upk2(u64 p, float& a, float& b) {
    asm("mov.b64 {%0, %1}, %2;" : "=f"(a), "=f"(b) : "l"(p));
}
__device__ __forceinline__ u64 add2(u64 a, u64 b) {
    u64 r; asm("add.rn.f32x2 %0, %1, %2;" : "=l"(r) : "l"(a), "l"(b)); return r;
}
__device__ __forceinline__ u64 sub2(u64 a, u64 b) {
    u64 r; asm("sub.rn.f32x2 %0, %1, %2;" : "=l"(r) : "l"(a), "l"(b)); return r;
}
__device__ __forceinline__ u64 mul2(u64 a, u64 b) {
    u64 r; asm("mul.rn.f32x2 %0, %1, %2;" : "=l"(r) : "l"(a), "l"(b)); return r;
}
__device__ __forceinline__ u64 fma2(u64 a, u64 b, u64 c) {
    u64 r; asm("fma.rn.f32x2 %0, %1, %2, %3;" : "=l"(r) : "l"(a), "l"(b), "l"(c)); return r;
}
__device__ __forceinline__ u64 abs2(u64 a) {
    u64 r; asm("and.b64 %0, %1, 0x7FFFFFFF7FFFFFFF;" : "=l"(r) : "l"(a)); return r;
}

__device__ __forceinline__ float ftanh(float x) {
    float t; asm("tanh.approx.f32 %0, %1;" : "=f"(t) : "f"(x)); return t;
}
__device__ __forceinline__ float fsig(float x) {           // scalar sigmoid
    return fmaf(0.5f, ftanh(0.5f * x), 0.5f);
}
__device__ __forceinline__ float fsqrt_fast(float x) {
    float r; asm("sqrt.approx.f32 %0, %1;" : "=f"(r) : "f"(x)); return r;
}

// ---------------------------------------------------------------------------
// score = ALPHA * sum(edge) + (1-ALPHA)/49 * sum( cnt(p) * (m_p - mean_p)^2 )
// R5 structure (smem row exchange, 1-row LDG prefetch, static clean path for
// interior blocks), with the clean path's column math packed into f32x2 pairs.
// ---------------------------------------------------------------------------
__global__ __launch_bounds__(256, 2) void score_kernel(const float* __restrict__ logits) {
    __shared__ float rowbuf[2][1032];   // cols -4..1027, data at offset 4
    __shared__ float red[8];

    const int img = blockIdx.y;
    const int y0  = blockIdx.x * RPB;
    const int t   = threadIdx.x;
    const int c0  = t * 4;
    const float* base = logits + (size_t)img * (IMG_H * IMG_W);

    // zero pad columns of both buffers (written once)
    if (t < 16) {
        int b = t >> 3, j = t & 7;
        rowbuf[b][(j < 4) ? j : (1020 + j)] = 0.0f;
    }

    float acc;

    if (blockIdx.x >= 1 && blockIdx.x <= 14) {
        // ================= clean path (f32x2): rows in-bounds, chf = 7 =====
        const u64 HALF2  = pk2(0.5f, 0.5f);
        const u64 TWO2   = pk2(2.0f, 2.0f);
        const u64 N6_2   = pk2(-6.0f, -6.0f);
        const u64 NI49_2 = pk2(-(1.0f / 49.0f), -(1.0f / 49.0f));

        float cwn[4];
        #pragma unroll
        for (int j = 0; j < 4; ++j) {
            int col = c0 + j;
            cwn[j] = (float)(min(col, 3) + min(IMG_W - 1 - col, 3) + 1) * (1.0f / 7.0f);
        }
        const u64 CN01 = pk2(cwn[0], cwn[1]);
        const u64 CN23 = pk2(cwn[2], cwn[3]);

        u64 hr01[8], hr23[8];                 // h-sum ring (pairs)
        u64 RS01[4], RS23[4], RT01[4], RT23[4], RC01[4], RC23[4];
        u64 vs01 = 0ull, vs23 = 0ull;
        u64 acc_l01 = 0ull, acc_l23 = 0ull;
        u64 acc_v01 = 0ull, acc_v23 = 0ull;
        float acc_e = 0.f;
        #pragma unroll
        for (int k = 0; k < 8; ++k) { hr01[k] = 0ull; hr23[k] = 0ull; }
        #pragma unroll
        for (int k = 0; k < 4; ++k) {
            RS01[k] = RS23[k] = RT01[k] = RT23[k] = RC01[k] = RC23[k] = 0ull;
        }

        const float* rp = base + (size_t)(y0 - 3) * IMG_W + c0;
        float4 cur = *(const float4*)rp; rp += IMG_W;   // row i=0

#define ROW_CLEAN(U, DOOUT, DOPREF)                                         \
    do {                                                                    \
        float4 nxt;                                                         \
        if (DOPREF) { nxt = *(const float4*)rp; rp += IMG_W; }              \
        else        { nxt = make_float4(0.f, 0.f, 0.f, 0.f); }              \
        /* sigmoid: paired mul/fma around scalar tanh */                    \
        u64 x01 = mul2(pk2(cur.x, cur.y), HALF2);                           \
        u64 x23 = mul2(pk2(cur.z, cur.w), HALF2);                           \
        float t0, t1, t2, t3;                                               \
        upk2(x01, t0, t1); upk2(x23, t2, t3);                               \
        u64 s01 = fma2(HALF2, pk2(ftanh(t0), ftanh(t1)), HALF2);            \
        u64 s23 = fma2(HALF2, pk2(ftanh(t2), ftanh(t3)), HALF2);            \
        float m0, m1, m2, m3;                                               \
        upk2(s01, m0, m1); upk2(s23, m2, m3);                               \
        float* rb = rowbuf[(U) & 1];                                        \
        *(float4*)(rb + 4 + c0) = make_float4(m0, m1, m2, m3);              \
        __syncthreads();                                                    \
        const float4 A = *(const float4*)(rb + c0);                         \
        const float4 B = *(const float4*)(rb + c0 + 4);                     \
        const float4 C = *(const float4*)(rb + c0 + 8);                     \
        float h0 = ((A.y + A.z) + (A.w + B.x)) + ((B.y + B.z) + B.w);       \
        float h1 = h0 + C.x - A.y;                                          \
        float h2 = h1 + C.y - A.z;                                          \
        float h3 = h2 + C.z - A.w;                                          \
        u64 H01 = pk2(h0, h1), H23 = pk2(h2, h3);                           \
        vs01 = add2(vs01, sub2(H01, hr01[((U) + 1) & 7]));                  \
        vs23 = add2(vs23, sub2(H23, hr23[((U) + 1) & 7]));                  \
        hr01[(U) & 7] = H01; hr23[(U) & 7] = H23;                           \
        if (DOOUT) {                                                        \
            const int T = (U) & 3, M = ((U) + 1) & 3, Bo = ((U) + 2) & 3;   \
            u64 gx01 = fma2(TWO2, RT01[M], add2(RT01[T], RT01[Bo]));        \
            u64 gy01 = sub2(RS01[T], RS01[Bo]);                             \
            u64 lp01 = fma2(N6_2, RC01[M],                                  \
                            add2(add2(RC01[T], RC01[Bo]), RS01[M]));        \
            u64 q01  = fma2(gx01, gx01, mul2(gy01, gy01));                  \
            float qa, qb; upk2(q01, qa, qb);                                \
            acc_e += fsqrt_fast(qa) + fsqrt_fast(qb);                       \
            acc_l01 = add2(acc_l01, abs2(lp01));                            \
            u64 d01 = fma2(NI49_2, vs01, RC01[M]);                          \
            acc_v01 = fma2(mul2(d01, CN01), d01, acc_v01);                  \
            u64 gx23 = fma2(TWO2, RT23[M], add2(RT23[T], RT23[Bo]));        \
            u64 gy23 = sub2(RS23[T], RS23[Bo]);                             \
            u64 lp23 = fma2(N6_2, RC23[M],                                  \
                            add2(add2(RC23[T], RC23[Bo]), RS23[M]));        \
            u64 q23  = fma2(gx23, gx23, mul2(gy23, gy23));                  \
            float qc, qd; upk2(q23, qc, qd);                                \
            acc_e += fsqrt_fast(qc) + fsqrt_fast(qd);                       \
            acc_l23 = add2(acc_l23, abs2(lp23));                            \
            u64 d23 = fma2(NI49_2, vs23, RC23[M]);                          \
            acc_v23 = fma2(mul2(d23, CN23), d23, acc_v23);                  \
        }                                                                   \
        { /* conv combos for row U (pairs) */                               \
            const int W = (U) & 3;                                          \
            u64 M01 = pk2(B.x, B.y), M23 = pk2(B.z, B.w);                   \
            u64 Lm  = pk2(A.w, B.x);                                        \
            u64 M12 = pk2(B.y, B.z);                                        \
            u64 M34 = pk2(B.w, C.x);                                        \
            RS01[W] = fma2(TWO2, M01, add2(Lm, M12));                       \
            RS23[W] = fma2(TWO2, M23, add2(M12, M34));                      \
            RT01[W] = sub2(Lm, M12);                                        \
            RT23[W] = sub2(M12, M34);                                       \
            RC01[W] = M01; RC23[W] = M23;                                   \
        }                                                                   \
        cur = nxt;                                                          \
    } while (0)

        // prologue rows 0..7 (output only rows 6,7)
        ROW_CLEAN(0, false, true); ROW_CLEAN(1, false, true);
        ROW_CLEAN(2, false, true); ROW_CLEAN(3, false, true);
        ROW_CLEAN(4, false, true); ROW_CLEAN(5, false, true);
        ROW_CLEAN(6, true,  true); ROW_CLEAN(7, true,  true);

        // middle rows 8..63
        for (int ii = 8; ii < 64; ii += 8) {
            ROW_CLEAN(0, true, true); ROW_CLEAN(1, true, true);
            ROW_CLEAN(2, true, true); ROW_CLEAN(3, true, true);
            ROW_CLEAN(4, true, true); ROW_CLEAN(5, true, true);
            ROW_CLEAN(6, true, true); ROW_CLEAN(7, true, true);
        }

        // tail rows 64..69 (last prefetch at row 68)
        ROW_CLEAN(0, true, true); ROW_CLEAN(1, true, true);
        ROW_CLEAN(2, true, true); ROW_CLEAN(3, true, true);
        ROW_CLEAN(4, true, true); ROW_CLEAN(5, true, false);
#undef ROW_CLEAN

        float l0, l1, l2, l3, v0, v1, v2, v3;
        upk2(acc_l01, l0, l1); upk2(acc_l23, l2, l3);
        upk2(acc_v01, v0, v1); upk2(acc_v23, v2, v3);
        float acc_e_tot = acc_e + 0.5f * ((l0 + l1) + (l2 + l3));
        float acc_v_tot = (v0 + v1) + (v2 + v3);
        acc = AALPHA * acc_e_tot + ((1.0f - AALPHA) / 49.0f) * 7.0f * acc_v_tot;
    } else {
        // ================= guarded path (blocks 0 and 15), scalar ==========
        float hr[8][4];
        float rs[4][4], rt[4][4], rc[4][4];
        float vs[4] = {0.f, 0.f, 0.f, 0.f};
        float acc_e = 0.f, acc_v = 0.f;
        #pragma unroll
        for (int k = 0; k < 8; ++k) { hr[k][0]=hr[k][1]=hr[k][2]=hr[k][3]=0.f; }
        #pragma unroll
        for (int k = 0; k < 4; ++k) {
            #pragma unroll
            for (int j = 0; j < 4; ++j) { rs[k][j]=0.f; rt[k][j]=0.f; rc[k][j]=0.f; }
        }
        float cwf[4];
        #pragma unroll
        for (int j = 0; j < 4; ++j) {
            int col = c0 + j;
            cwf[j] = (float)(min(col, 3) + min(IMG_W - 1 - col, 3) + 1);
        }

        float4 cur = make_float4(0.f, 0.f, 0.f, 0.f);
        {
            int gy = y0 - 3;
            if ((unsigned)gy < IMG_H)
                cur = *(const float4*)(base + (size_t)gy * IMG_W + c0);
        }
        for (int ii = 0; ii < 72; ii += 8) {
            #pragma unroll
            for (int u = 0; u < 8; ++u) {
                const int i  = ii + u;
                const int gy = y0 - 3 + i;
                const bool valid = ((unsigned)gy < IMG_H) && (i < 70);

                float4 nxt = make_float4(0.f, 0.f, 0.f, 0.f);
                {
                    int gyn = gy + 1;
                    if ((unsigned)gyn < IMG_H && (i + 1) < 70)
                        nxt = *(const float4*)(base + (size_t)gyn * IMG_W + c0);
                }
                float m0 = valid ? fsig(cur.x) : 0.f;
                float m1 = valid ? fsig(cur.y) : 0.f;
                float m2 = valid ? fsig(cur.z) : 0.f;
                float m3 = valid ? fsig(cur.w) : 0.f;
                float* rb = rowbuf[u & 1];
                *(float4*)(rb + 4 + c0) = make_float4(m0, m1, m2, m3);
                __syncthreads();

                const float4 A = *(const float4*)(rb + c0);
                const float4 B = *(const float4*)(rb + c0 + 4);
                const float4 C = *(const float4*)(rb + c0 + 8);

                float h0 = ((A.y + A.z) + (A.w + B.x)) + ((B.y + B.z) + B.w);
                float h1 = h0 + C.x - A.y;
                float h2 = h1 + C.y - A.z;
                float h3 = h2 + C.z - A.w;

                vs[0] += h0 - hr[(u + 1) & 7][0];
                vs[1] += h1 - hr[(u + 1) & 7][1];
                vs[2] += h2 - hr[(u + 1) & 7][2];
                vs[3] += h3 - hr[(u + 1) & 7][3];
                hr[u][0] = h0; hr[u][1] = h1; hr[u][2] = h2; hr[u][3] = h3;

                if (i >= 6 && i < 70) {
                    const int yo = gy - 3;
                    const float chf = (float)(min(yo, 3) + min(IMG_H - 1 - yo, 3) + 1);
                    const int T = u & 3, M = (u + 1) & 3, Bo = (u + 2) & 3;
                    float rowv = 0.f;
                    #pragma unroll
                    for (int j = 0; j < 4; ++j) {
                        float gxv = fmaf(2.f, rt[M][j], rt[T][j] + rt[Bo][j]);
                        float gyv = rs[T][j] - rs[Bo][j];
                        float lap = fmaf(-6.f, rc[M][j], (rc[T][j] + rc[Bo][j]) + rs[M][j]);
                        acc_e += fsqrt_fast(fmaf(gxv, gxv, gyv * gyv)) + 0.5f * fabsf(lap);
                        float d = fmaf(-(1.f / 49.f), vs[j], rc[M][j]);
                        rowv = fmaf(d * cwf[j], d, rowv);
                    }
                    acc_v += chf * rowv;
                }

                const int W = u & 3;
                rs[W][0] = fmaf(2.f, B.x, A.w + B.y); rt[W][0] = A.w - B.y; rc[W][0] = B.x;
                rs[W][1] = fmaf(2.f, B.y, B.x + B.z); rt[W][1] = B.x - B.z; rc[W][1] = B.y;
                rs[W][2] = fmaf(2.f, B.z, B.y + B.w); rt[W][2] = B.y - B.w; rc[W][2] = B.z;
                rs[W][3] = fmaf(2.f, B.w, B.z + C.x); rt[W][3] = B.z - C.x; rc[W][3] = B.w;

                cur = nxt;
            }
        }
        acc = AALPHA * acc_e + ((1.0f - AALPHA) / 49.0f) * acc_v;
    }

    // block reduction -> per-block partial
    #pragma unroll
    for (int off = 16; off; off >>= 1)
        acc += __shfl_down_sync(0xffffffffu, acc, off);
    if ((t & 31) == 0) red[t >> 5] = acc;
    __syncthreads();
    if (t < 8) {
        float v = red[t];
        #pragma unroll
        for (int off = 4; off; off >>= 1)
            v += __shfl_down_sync(0xffu, v, off);
        if (t == 0) g_part[img * BPI + blockIdx.x] = v;
    }
}

// ---------------------------------------------------------------------------
// reduce partials; weights[b,s] = 0.5*(score/(sum+1e-6) + softmax(lw)[s])
// ---------------------------------------------------------------------------
__global__ void weights_kernel(const float* __restrict__ lw) {
    __shared__ float ss[NIMG];
    __shared__ float soft[3];
    int tid = threadIdx.x;
    if (tid < NIMG) {
        float s = 0.f;
        #pragma unroll
        for (int k = 0; k < BPI; ++k) s += g_part[tid * BPI + k];
        ss[tid] = s;
    }
    if (tid == 0) {
        float a = lw[0], b = lw[1], c = lw[2];
        float m = fmaxf(a, fmaxf(b, c));
        float e0 = expf(a - m), e1 = expf(b - m), e2 = expf(c - m);
        float inv = 1.0f / (e0 + e1 + e2);
        soft[0] = e0 * inv; soft[1] = e1 * inv; soft[2] = e2 * inv;
    }
    __syncthreads();
    if (tid < NIMG) {
        int b = tid / 3;
        int s = tid - b * 3;
        float denom = ss[b * 3] + ss[b * 3 + 1] + ss[b * 3 + 2] + 1e-6f;
        g_weights[tid] = (ss[tid] / denom + soft[s]) * 0.5f;
    }
}

// ---------------------------------------------------------------------------
// fused[b,p] = sum_s logits[b,s,p] * w[b,s]   (float4 vectorized)
// ---------------------------------------------------------------------------
__global__ __launch_bounds__(256) void fuse_kernel(const float* __restrict__ logits,
                                                   float* __restrict__ out) {
    const int N = IMG_H * IMG_W;
    int b = blockIdx.y;
    int i = blockIdx.x * blockDim.x + threadIdx.x;   // over N/4
    float w0 = g_weights[b * 3 + 0];
    float w1 = g_weights[b * 3 + 1];
    float w2 = g_weights[b * 3 + 2];
    const float4* p0 = (const float4*)(logits + (size_t)(b * 3 + 0) * N);
    const float4* p1 = (const float4*)(logits + (size_t)(b * 3 + 1) * N);
    const float4* p2 = (const float4*)(logits + (size_t)(b * 3 + 2) * N);
    float4 a = p0[i], bb = p1[i], cc = p2[i];
    float4 o;
    o.x = a.x * w0 + bb.x * w1 + cc.x * w2;
    o.y = a.y * w0 + bb.y * w1 + cc.y * w2;
    o.z = a.z * w0 + bb.z * w1 + cc.z * w2;
    o.w = a.w * w0 + bb.w * w1 + cc.w * w2;
    ((float4*)out)[(size_t)b * (N / 4) + i] = o;
}

extern "C" void kernel_launch(void* const* d_in, const int* in_sizes, int n_in,
                              void* d_out, int out_size) {
    const float* logits = (const float*)d_in[0];   // (16,3,1024,1024) fp32
    const float* lw     = (const float*)d_in[1];   // (3,) fp32
    float* out          = (float*)d_out;           // (16,1024,1024) fp32

    score_kernel<<<dim3(BPI, NIMG), 256>>>(logits);
    weights_kernel<<<1, 64>>>(lw);
    fuse_kernel<<<dim3((IMG_H * IMG_W / 4) / 256, 16), 256>>>(logits, out);
}

// round 8
// speedup vs baseline: 1.5273x; 1.0394x over previous
#include <cuda_runtime.h>

#define AALPHA 0.42f
#define IMG_H 1024
#define IMG_W 1024
#define NIMG 48     // 16 batches * 3 masks
#define RPB 64      // output rows per block
#define BPI 16      // blocks per image (IMG_H / RPB)

__device__ float g_part[NIMG * BPI];
__device__ float g_weights[NIMG];

// sigmoid(x) = 0.5*tanh(x/2)+0.5  (1 MUFU + 2 fma)
__device__ __forceinline__ float fsig(float x) {
    float t;
    asm("tanh.approx.f32 %0, %1;" : "=f"(t) : "f"(0.5f * x));
    return fmaf(0.5f, t, 0.5f);
}
__device__ __forceinline__ float fsqrt_fast(float x) {
    float r; asm("sqrt.approx.f32 %0, %1;" : "=f"(r) : "f"(x)); return r;
}

// ---------------------------------------------------------------------------
// score = ALPHA * sum(edge) + (1-ALPHA)/49 * sum( cnt(p) * (m_p - mean_p)^2 )
// R5 structure + TWO ROWS PER BARRIER: sigmoid+STS rows 2p,2p+1 -> one
// __syncthreads -> consume both rows. 4 smem row buffers (pair double-buffer,
// buffer pair = U&2). 1-pair LDG prefetch. Interior blocks: static clean path
// (chf=7 folded); blocks 0/15: guarded per-row path.
// ---------------------------------------------------------------------------
__global__ __launch_bounds__(256, 2) void score_kernel(const float* __restrict__ logits) {
    __shared__ float rowbuf[4][1032];   // cols -4..1027, data at offset 4
    __shared__ float red[8];

    const int img = blockIdx.y;
    const int y0  = blockIdx.x * RPB;
    const int t   = threadIdx.x;
    const int c0  = t * 4;
    const float* base = logits + (size_t)img * (IMG_H * IMG_W);

    // zero pad columns of all four buffers (written once)
    if (t < 32) {
        int b = t >> 3, j = t & 7;
        rowbuf[b][(j < 4) ? j : (1020 + j)] = 0.0f;
    }

    float hr[8][4];                      // horizontal-7-sum ring
    float rs[4][4], rt[4][4], rc[4][4];  // conv combo ring
    float vs[4] = {0.f, 0.f, 0.f, 0.f};
    #pragma unroll
    for (int k = 0; k < 8; ++k) { hr[k][0]=hr[k][1]=hr[k][2]=hr[k][3]=0.f; }
    #pragma unroll
    for (int k = 0; k < 4; ++k) {
        #pragma unroll
        for (int j = 0; j < 4; ++j) { rs[k][j]=0.f; rt[k][j]=0.f; rc[k][j]=0.f; }
    }

    float acc_e = 0.f, acc_v = 0.f, acc;

// consume one row from smem buffer RB; U = row ring index (static)
#define CONSUME(U, RB, DOOUT, CWMUL)                                        \
    do {                                                                    \
        const float4 A = *(const float4*)((RB) + c0);                       \
        const float4 B = *(const float4*)((RB) + c0 + 4);                   \
        const float4 C = *(const float4*)((RB) + c0 + 8);                   \
        float h0 = ((A.y + A.z) + (A.w + B.x)) + ((B.y + B.z) + B.w);       \
        float h1 = h0 + C.x - A.y;                                          \
        float h2 = h1 + C.y - A.z;                                          \
        float h3 = h2 + C.z - A.w;                                          \
        vs[0] += h0 - hr[((U) + 1) & 7][0];                                 \
        vs[1] += h1 - hr[((U) + 1) & 7][1];                                 \
        vs[2] += h2 - hr[((U) + 1) & 7][2];                                 \
        vs[3] += h3 - hr[((U) + 1) & 7][3];                                 \
        hr[(U) & 7][0] = h0; hr[(U) & 7][1] = h1;                           \
        hr[(U) & 7][2] = h2; hr[(U) & 7][3] = h3;                           \
        if (DOOUT) {                                                        \
            const int T = (U) & 3, M = ((U) + 1) & 3, Bo = ((U) + 2) & 3;   \
            float rowv = 0.f;                                               \
            _Pragma("unroll")                                               \
            for (int j = 0; j < 4; ++j) {                                   \
                float gxv = fmaf(2.f, rt[M][j], rt[T][j] + rt[Bo][j]);      \
                float gyv = rs[T][j] - rs[Bo][j];                           \
                float lap = fmaf(-6.f, rc[M][j],                            \
                                 (rc[T][j] + rc[Bo][j]) + rs[M][j]);        \
                acc_e += fsqrt_fast(fmaf(gxv, gxv, gyv * gyv))              \
                         + 0.5f * fabsf(lap);                               \
                float d = fmaf(-(1.f / 49.f), vs[j], rc[M][j]);             \
                rowv = fmaf(d * (CWMUL)[j], d, rowv);                       \
            }                                                               \
            acc_v += rowv;                                                  \
        }                                                                   \
        const int W = (U) & 3;                                              \
        rs[W][0] = fmaf(2.f, B.x, A.w + B.y); rt[W][0] = A.w - B.y; rc[W][0] = B.x; \
        rs[W][1] = fmaf(2.f, B.y, B.x + B.z); rt[W][1] = B.x - B.z; rc[W][1] = B.y; \
        rs[W][2] = fmaf(2.f, B.z, B.y + B.w); rt[W][2] = B.y - B.w; rc[W][2] = B.z; \
        rs[W][3] = fmaf(2.f, B.w, B.z + C.x); rt[W][3] = B.z - C.x; rc[W][3] = B.w; \
    } while (0)

    if (blockIdx.x >= 1 && blockIdx.x <= 14) {
        // ================= clean path: all rows in-bounds, chf = 7 =========
        float cwn[4];   // cw/7, ==1 except near image edge columns
        #pragma unroll
        for (int j = 0; j < 4; ++j) {
            int col = c0 + j;
            cwn[j] = (float)(min(col, 3) + min(IMG_W - 1 - col, 3) + 1) * (1.0f / 7.0f);
        }

        const float* rp = base + (size_t)(y0 - 3) * IMG_W + c0;
        float4 cur0 = *(const float4*)rp;
        float4 cur1 = *(const float4*)(rp + IMG_W);
        rp += 2 * IMG_W;

// process rows U,U+1 (U even, static); buffer pair = U&2
#define PAIR(U, DOOUT, DOPREF)                                              \
    do {                                                                    \
        float4 n0, n1;                                                      \
        if (DOPREF) {                                                       \
            n0 = *(const float4*)rp;                                        \
            n1 = *(const float4*)(rp + IMG_W);                              \
            rp += 2 * IMG_W;                                                \
        } else {                                                            \
            n0 = make_float4(0.f, 0.f, 0.f, 0.f); n1 = n0;                  \
        }                                                                   \
        float a0 = fsig(cur0.x), a1 = fsig(cur0.y);                         \
        float a2 = fsig(cur0.z), a3 = fsig(cur0.w);                         \
        float b0 = fsig(cur1.x), b1 = fsig(cur1.y);                         \
        float b2 = fsig(cur1.z), b3 = fsig(cur1.w);                         \
        float* rb0 = rowbuf[(U) & 2];                                       \
        float* rb1 = rowbuf[((U) & 2) + 1];                                 \
        *(float4*)(rb0 + 4 + c0) = make_float4(a0, a1, a2, a3);             \
        *(float4*)(rb1 + 4 + c0) = make_float4(b0, b1, b2, b3);             \
        __syncthreads();                                                    \
        CONSUME((U),     rb0, DOOUT, cwn);                                  \
        CONSUME((U) + 1, rb1, DOOUT, cwn);                                  \
        cur0 = n0; cur1 = n1;                                               \
    } while (0)

        // prologue pairs: rows 0..7 (outputs only at rows 6,7)
        PAIR(0, false, true); PAIR(2, false, true);
        PAIR(4, false, true); PAIR(6, true,  true);

        // middle pairs: rows 8..63 (28 pairs = 7 x 4)
        for (int ii = 0; ii < 7; ++ii) {
            PAIR(0, true, true); PAIR(2, true, true);
            PAIR(4, true, true); PAIR(6, true, true);
        }

        // tail pairs: rows 64..69 (pair of rows 66,67 prefetches rows 70,71 —
        // in-bounds for interior blocks, values discarded)
        PAIR(0, true, true); PAIR(2, true, true); PAIR(4, true, false);
#undef PAIR

        acc = AALPHA * acc_e + ((1.0f - AALPHA) / 49.0f) * 7.0f * acc_v;
    } else {
        // ================= guarded path (blocks 0 and 15), per-row =========
        float cwf[4];
        #pragma unroll
        for (int j = 0; j < 4; ++j) {
            int col = c0 + j;
            cwf[j] = (float)(min(col, 3) + min(IMG_W - 1 - col, 3) + 1);
        }

        float4 cur = make_float4(0.f, 0.f, 0.f, 0.f);
        {
            int gy = y0 - 3;
            if ((unsigned)gy < IMG_H)
                cur = *(const float4*)(base + (size_t)gy * IMG_W + c0);
        }
        for (int ii = 0; ii < 72; ii += 8) {
            #pragma unroll
            for (int u = 0; u < 8; ++u) {
                const int i  = ii + u;
                const int gy = y0 - 3 + i;
                const bool valid = ((unsigned)gy < IMG_H) && (i < 70);

                float4 nxt = make_float4(0.f, 0.f, 0.f, 0.f);
                {
                    int gyn = gy + 1;
                    if ((unsigned)gyn < IMG_H && (i + 1) < 70)
                        nxt = *(const float4*)(base + (size_t)gyn * IMG_W + c0);
                }
                float m0 = valid ? fsig(cur.x) : 0.f;
                float m1 = valid ? fsig(cur.y) : 0.f;
                float m2 = valid ? fsig(cur.z) : 0.f;
                float m3 = valid ? fsig(cur.w) : 0.f;
                float* rb = rowbuf[u & 1];
                *(float4*)(rb + 4 + c0) = make_float4(m0, m1, m2, m3);
                __syncthreads();

                const float4 A = *(const float4*)(rb + c0);
                const float4 B = *(const float4*)(rb + c0 + 4);
                const float4 C = *(const float4*)(rb + c0 + 8);

                float h0 = ((A.y + A.z) + (A.w + B.x)) + ((B.y + B.z) + B.w);
                float h1 = h0 + C.x - A.y;
                float h2 = h1 + C.y - A.z;
                float h3 = h2 + C.z - A.w;

                vs[0] += h0 - hr[(u + 1) & 7][0];
                vs[1] += h1 - hr[(u + 1) & 7][1];
                vs[2] += h2 - hr[(u + 1) & 7][2];
                vs[3] += h3 - hr[(u + 1) & 7][3];
                hr[u][0] = h0; hr[u][1] = h1; hr[u][2] = h2; hr[u][3] = h3;

                if (i >= 6 && i < 70) {
                    const int yo = gy - 3;
                    const float chf = (float)(min(yo, 3) + min(IMG_H - 1 - yo, 3) + 1);
                    const int T = u & 3, M = (u + 1) & 3, Bo = (u + 2) & 3;
                    float rowv = 0.f;
                    #pragma unroll
                    for (int j = 0; j < 4; ++j) {
                        float gxv = fmaf(2.f, rt[M][j], rt[T][j] + rt[Bo][j]);
                        float gyv = rs[T][j] - rs[Bo][j];
                        float lap = fmaf(-6.f, rc[M][j], (rc[T][j] + rc[Bo][j]) + rs[M][j]);
                        acc_e += fsqrt_fast(fmaf(gxv, gxv, gyv * gyv)) + 0.5f * fabsf(lap);
                        float d = fmaf(-(1.f / 49.f), vs[j], rc[M][j]);
                        rowv = fmaf(d * cwf[j], d, rowv);
                    }
                    acc_v += chf * rowv;
                }

                const int W = u & 3;
                rs[W][0] = fmaf(2.f, B.x, A.w + B.y); rt[W][0] = A.w - B.y; rc[W][0] = B.x;
                rs[W][1] = fmaf(2.f, B.y, B.x + B.z); rt[W][1] = B.x - B.z; rc[W][1] = B.y;
                rs[W][2] = fmaf(2.f, B.z, B.y + B.w); rt[W][2] = B.y - B.w; rc[W][2] = B.z;
                rs[W][3] = fmaf(2.f, B.w, B.z + C.x); rt[W][3] = B.z - C.x; rc[W][3] = B.w;

                cur = nxt;
            }
        }
        acc = AALPHA * acc_e + ((1.0f - AALPHA) / 49.0f) * acc_v;
    }
#undef CONSUME

    // block reduction -> per-block partial
    #pragma unroll
    for (int off = 16; off; off >>= 1)
        acc += __shfl_down_sync(0xffffffffu, acc, off);
    if ((t & 31) == 0) red[t >> 5] = acc;
    __syncthreads();
    if (t < 8) {
        float v = red[t];
        #pragma unroll
        for (int off = 4; off; off >>= 1)
            v += __shfl_down_sync(0xffu, v, off);
        if (t == 0) g_part[img * BPI + blockIdx.x] = v;
    }
}

// ---------------------------------------------------------------------------
// reduce partials; weights[b,s] = 0.5*(score/(sum+1e-6) + softmax(lw)[s])
// ---------------------------------------------------------------------------
__global__ void weights_kernel(const float* __restrict__ lw) {
    __shared__ float ss[NIMG];
    __shared__ float soft[3];
    int tid = threadIdx.x;
    if (tid < NIMG) {
        float s = 0.f;
        #pragma unroll
        for (int k = 0; k < BPI; ++k) s += g_part[tid * BPI + k];
        ss[tid] = s;
    }
    if (tid == 0) {
        float a = lw[0], b = lw[1], c = lw[2];
        float m = fmaxf(a, fmaxf(b, c));
        float e0 = expf(a - m), e1 = expf(b - m), e2 = expf(c - m);
        float inv = 1.0f / (e0 + e1 + e2);
        soft[0] = e0 * inv; soft[1] = e1 * inv; soft[2] = e2 * inv;
    }
    __syncthreads();
    if (tid < NIMG) {
        int b = tid / 3;
        int s = tid - b * 3;
        float denom = ss[b * 3] + ss[b * 3 + 1] + ss[b * 3 + 2] + 1e-6f;
        g_weights[tid] = (ss[tid] / denom + soft[s]) * 0.5f;
    }
}

// ---------------------------------------------------------------------------
// fused[b,p] = sum_s logits[b,s,p] * w[b,s]   (float4 vectorized)
// ---------------------------------------------------------------------------
__global__ __launch_bounds__(256) void fuse_kernel(const float* __restrict__ logits,
                                                   float* __restrict__ out) {
    const int N = IMG_H * IMG_W;
    int b = blockIdx.y;
    int i = blockIdx.x * blockDim.x + threadIdx.x;   // over N/4
    float w0 = g_weights[b * 3 + 0];
    float w1 = g_weights[b * 3 + 1];
    float w2 = g_weights[b * 3 + 2];
    const float4* p0 = (const float4*)(logits + (size_t)(b * 3 + 0) * N);
    const float4* p1 = (const float4*)(logits + (size_t)(b * 3 + 1) * N);
    const float4* p2 = (const float4*)(logits + (size_t)(b * 3 + 2) * N);
    float4 a = p0[i], bb = p1[i], cc = p2[i];
    float4 o;
    o.x = a.x * w0 + bb.x * w1 + cc.x * w2;
    o.y = a.y * w0 + bb.y * w1 + cc.y * w2;
    o.z = a.z * w0 + bb.z * w1 + cc.z * w2;
    o.w = a.w * w0 + bb.w * w1 + cc.w * w2;
    ((float4*)out)[(size_t)b * (N / 4) + i] = o;
}

extern "C" void kernel_launch(void* const* d_in, const int* in_sizes, int n_in,
                              void* d_out, int out_size) {
    const float* logits = (const float*)d_in[0];   // (16,3,1024,1024) fp32
    const float* lw     = (const float*)d_in[1];   // (3,) fp32
    float* out          = (float*)d_out;           // (16,1024,1024) fp32

    score_kernel<<<dim3(BPI, NIMG), 256>>>(logits);
    weights_kernel<<<1, 64>>>(lw);
    fuse_kernel<<<dim3((IMG_H * IMG_W / 4) / 256, 16), 256>>>(logits, out);
}

// round 9
// speedup vs baseline: 1.6360x; 1.0712x over previous
#include <cuda_runtime.h>

#define AALPHA 0.42f
#define IMG_H 1024
#define IMG_W 1024
#define NIMG 48     // 16 batches * 3 masks
#define RPB 64      // output rows per block
#define BPI 16      // blocks per image (IMG_H / RPB)

__device__ float g_part[NIMG * BPI];
__device__ float g_weights[NIMG];

// sigmoid(x) = 0.5*tanh(x/2)+0.5  (1 MUFU + 2 fma)
__device__ __forceinline__ float fsig(float x) {
    float t;
    asm("tanh.approx.f32 %0, %1;" : "=f"(t) : "f"(0.5f * x));
    return fmaf(0.5f, t, 0.5f);
}
__device__ __forceinline__ float fsqrt_fast(float x) {
    float r; asm("sqrt.approx.f32 %0, %1;" : "=f"(r) : "f"(x)); return r;
}

// ---------------------------------------------------------------------------
// score = ALPHA * sum(edge) + (1-ALPHA)/49 * sum( cnt(p) * (m_p - mean_p)^2 )
// Two rows per barrier; own 4 sigmoid values kept in registers (B never
// reloaded from smem) -> only 2 neighbor LDS.128 per row. |lap| and per-
// column d^2 go to separate accumulators; 0.5 / cw scalings folded at end.
// ---------------------------------------------------------------------------
__global__ __launch_bounds__(256, 2) void score_kernel(const float* __restrict__ logits) {
    __shared__ float rowbuf[4][1032];   // cols -4..1027, data at offset 4
    __shared__ float red[8];

    const int img = blockIdx.y;
    const int y0  = blockIdx.x * RPB;
    const int t   = threadIdx.x;
    const int c0  = t * 4;
    const float* base = logits + (size_t)img * (IMG_H * IMG_W);

    // zero pad columns of all four buffers (written once)
    if (t < 32) {
        int b = t >> 3, j = t & 7;
        rowbuf[b][(j < 4) ? j : (1020 + j)] = 0.0f;
    }

    float hr[8][4];                      // horizontal-7-sum ring
    float rs[4][4], rt[4][4], rc[4][4];  // conv combo ring
    float vs[4] = {0.f, 0.f, 0.f, 0.f};
    #pragma unroll
    for (int k = 0; k < 8; ++k) { hr[k][0]=hr[k][1]=hr[k][2]=hr[k][3]=0.f; }
    #pragma unroll
    for (int k = 0; k < 4; ++k) {
        #pragma unroll
        for (int j = 0; j < 4; ++j) { rs[k][j]=0.f; rt[k][j]=0.f; rc[k][j]=0.f; }
    }

    float acc;

// consume one row; M0..M3 = this row's sigmoid values (registers),
// RB = smem buffer holding this row (for neighbor halos). U static.
// ACCV = float[4] per-column d^2 accumulator, ACCE/ACCL scalars.
#define CONSUME(U, RB, M0, M1, M2, M3, DOOUT, ACCV, ACCE, ACCL)             \
    do {                                                                    \
        const float4 A = *(const float4*)((RB) + c0);       /* c0-4..c0-1 */\
        const float4 C = *(const float4*)((RB) + c0 + 8);   /* c0+4..c0+7 */\
        float h0 = ((A.y + A.z) + (A.w + M0)) + ((M1 + M2) + M3);           \
        float h1 = h0 + C.x - A.y;                                          \
        float h2 = h1 + C.y - A.z;                                          \
        float h3 = h2 + C.z - A.w;                                          \
        vs[0] += h0 - hr[((U) + 1) & 7][0];                                 \
        vs[1] += h1 - hr[((U) + 1) & 7][1];                                 \
        vs[2] += h2 - hr[((U) + 1) & 7][2];                                 \
        vs[3] += h3 - hr[((U) + 1) & 7][3];                                 \
        hr[(U) & 7][0] = h0; hr[(U) & 7][1] = h1;                           \
        hr[(U) & 7][2] = h2; hr[(U) & 7][3] = h3;                           \
        if (DOOUT) {                                                        \
            const int T = (U) & 3, M = ((U) + 1) & 3, Bo = ((U) + 2) & 3;   \
            _Pragma("unroll")                                               \
            for (int j = 0; j < 4; ++j) {                                   \
                float gxv = fmaf(2.f, rt[M][j], rt[T][j] + rt[Bo][j]);      \
                float gyv = rs[T][j] - rs[Bo][j];                           \
                float lap = fmaf(-6.f, rc[M][j],                            \
                                 (rc[T][j] + rc[Bo][j]) + rs[M][j]);        \
                ACCE += fsqrt_fast(fmaf(gxv, gxv, gyv * gyv));              \
                ACCL += fabsf(lap);                                         \
                float d = fmaf(-(1.f / 49.f), vs[j], rc[M][j]);             \
                (ACCV)[j] = fmaf(d, d, (ACCV)[j]);                          \
            }                                                               \
        }                                                                   \
        const int W = (U) & 3;                                              \
        rs[W][0] = fmaf(2.f, M0, A.w + M1); rt[W][0] = A.w - M1; rc[W][0] = M0; \
        rs[W][1] = fmaf(2.f, M1, M0 + M2);  rt[W][1] = M0 - M2;  rc[W][1] = M1; \
        rs[W][2] = fmaf(2.f, M2, M1 + M3);  rt[W][2] = M1 - M3;  rc[W][2] = M2; \
        rs[W][3] = fmaf(2.f, M3, M2 + C.x); rt[W][3] = M2 - C.x; rc[W][3] = M3; \
    } while (0)

    if (blockIdx.x >= 1 && blockIdx.x <= 14) {
        // ================= clean path: all rows in-bounds, chf = 7 =========
        float accv[4] = {0.f, 0.f, 0.f, 0.f};
        float acc_e = 0.f, acc_l = 0.f;

        const float* rp = base + (size_t)(y0 - 3) * IMG_W + c0;
        float4 cur0 = *(const float4*)rp;
        float4 cur1 = *(const float4*)(rp + IMG_W);
        rp += 2 * IMG_W;

// process rows U,U+1 (U even, static); buffer pair = U&2
#define PAIR(U, DOOUT, DOPREF)                                              \
    do {                                                                    \
        float4 n0, n1;                                                      \
        if (DOPREF) {                                                       \
            n0 = *(const float4*)rp;                                        \
            n1 = *(const float4*)(rp + IMG_W);                              \
            rp += 2 * IMG_W;                                                \
        } else {                                                            \
            n0 = make_float4(0.f, 0.f, 0.f, 0.f); n1 = n0;                  \
        }                                                                   \
        float a0 = fsig(cur0.x), a1 = fsig(cur0.y);                         \
        float a2 = fsig(cur0.z), a3 = fsig(cur0.w);                         \
        float b0 = fsig(cur1.x), b1 = fsig(cur1.y);                         \
        float b2 = fsig(cur1.z), b3 = fsig(cur1.w);                         \
        float* rb0 = rowbuf[(U) & 2];                                       \
        float* rb1 = rowbuf[((U) & 2) + 1];                                 \
        *(float4*)(rb0 + 4 + c0) = make_float4(a0, a1, a2, a3);             \
        *(float4*)(rb1 + 4 + c0) = make_float4(b0, b1, b2, b3);             \
        __syncthreads();                                                    \
        CONSUME((U),     rb0, a0, a1, a2, a3, DOOUT, accv, acc_e, acc_l);   \
        CONSUME((U) + 1, rb1, b0, b1, b2, b3, DOOUT, accv, acc_e, acc_l);   \
        cur0 = n0; cur1 = n1;                                               \
    } while (0)

        // prologue pairs: rows 0..7 (outputs only at rows 6,7)
        PAIR(0, false, true); PAIR(2, false, true);
        PAIR(4, false, true); PAIR(6, true,  true);

        // middle pairs: rows 8..63 (28 pairs = 7 x 4)
        for (int ii = 0; ii < 7; ++ii) {
            PAIR(0, true, true); PAIR(2, true, true);
            PAIR(4, true, true); PAIR(6, true, true);
        }

        // tail pairs: rows 64..69 (rows 70,71 prefetched in-bounds, unused)
        PAIR(0, true, true); PAIR(2, true, true); PAIR(4, true, false);
#undef PAIR

        // fold cw/7 per column and 0.5*|lap| at the end
        float acc_v_tot = 0.f;
        #pragma unroll
        for (int j = 0; j < 4; ++j) {
            int col = c0 + j;
            float cwn = (float)(min(col, 3) + min(IMG_W - 1 - col, 3) + 1) * (1.0f / 7.0f);
            acc_v_tot = fmaf(accv[j], cwn, acc_v_tot);
        }
        float acc_e_tot = fmaf(0.5f, acc_l, acc_e);
        acc = AALPHA * acc_e_tot + ((1.0f - AALPHA) / 49.0f) * 7.0f * acc_v_tot;
    } else {
        // ================= guarded path (blocks 0 and 15), per-row =========
        float accv[4] = {0.f, 0.f, 0.f, 0.f};   // per-col, chf folded per-row
        float acc_e = 0.f, acc_l = 0.f, acc_v = 0.f;
        float cwf[4];
        #pragma unroll
        for (int j = 0; j < 4; ++j) {
            int col = c0 + j;
            cwf[j] = (float)(min(col, 3) + min(IMG_W - 1 - col, 3) + 1);
        }
        (void)accv;

        float4 cur = make_float4(0.f, 0.f, 0.f, 0.f);
        {
            int gy = y0 - 3;
            if ((unsigned)gy < IMG_H)
                cur = *(const float4*)(base + (size_t)gy * IMG_W + c0);
        }
        for (int ii = 0; ii < 72; ii += 8) {
            #pragma unroll
            for (int u = 0; u < 8; ++u) {
                const int i  = ii + u;
                const int gy = y0 - 3 + i;
                const bool valid = ((unsigned)gy < IMG_H) && (i < 70);

                float4 nxt = make_float4(0.f, 0.f, 0.f, 0.f);
                {
                    int gyn = gy + 1;
                    if ((unsigned)gyn < IMG_H && (i + 1) < 70)
                        nxt = *(const float4*)(base + (size_t)gyn * IMG_W + c0);
                }
                float m0 = valid ? fsig(cur.x) : 0.f;
                float m1 = valid ? fsig(cur.y) : 0.f;
                float m2 = valid ? fsig(cur.z) : 0.f;
                float m3 = valid ? fsig(cur.w) : 0.f;
                float* rb = rowbuf[u & 1];
                *(float4*)(rb + 4 + c0) = make_float4(m0, m1, m2, m3);
                __syncthreads();

                const float4 A = *(const float4*)(rb + c0);
                const float4 C = *(const float4*)(rb + c0 + 8);

                float h0 = ((A.y + A.z) + (A.w + m0)) + ((m1 + m2) + m3);
                float h1 = h0 + C.x - A.y;
                float h2 = h1 + C.y - A.z;
                float h3 = h2 + C.z - A.w;

                vs[0] += h0 - hr[(u + 1) & 7][0];
                vs[1] += h1 - hr[(u + 1) & 7][1];
                vs[2] += h2 - hr[(u + 1) & 7][2];
                vs[3] += h3 - hr[(u + 1) & 7][3];
                hr[u][0] = h0; hr[u][1] = h1; hr[u][2] = h2; hr[u][3] = h3;

                if (i >= 6 && i < 70) {
                    const int yo = gy - 3;
                    const float chf = (float)(min(yo, 3) + min(IMG_H - 1 - yo, 3) + 1);
                    const int T = u & 3, M = (u + 1) & 3, Bo = (u + 2) & 3;
                    float rowv = 0.f;
                    #pragma unroll
                    for (int j = 0; j < 4; ++j) {
                        float gxv = fmaf(2.f, rt[M][j], rt[T][j] + rt[Bo][j]);
                        float gyv = rs[T][j] - rs[Bo][j];
                        float lap = fmaf(-6.f, rc[M][j], (rc[T][j] + rc[Bo][j]) + rs[M][j]);
                        acc_e += fsqrt_fast(fmaf(gxv, gxv, gyv * gyv));
                        acc_l += fabsf(lap);
                        float d = fmaf(-(1.f / 49.f), vs[j], rc[M][j]);
                        rowv = fmaf(d * cwf[j], d, rowv);
                    }
                    acc_v += chf * rowv;
                }

                const int W = u & 3;
                rs[W][0] = fmaf(2.f, m0, A.w + m1); rt[W][0] = A.w - m1; rc[W][0] = m0;
                rs[W][1] = fmaf(2.f, m1, m0 + m2);  rt[W][1] = m0 - m2;  rc[W][1] = m1;
                rs[W][2] = fmaf(2.f, m2, m1 + m3);  rt[W][2] = m1 - m3;  rc[W][2] = m2;
                rs[W][3] = fmaf(2.f, m3, m2 + C.x); rt[W][3] = m2 - C.x; rc[W][3] = m3;

                cur = nxt;
            }
        }
        float acc_e_tot = fmaf(0.5f, acc_l, acc_e);
        acc = AALPHA * acc_e_tot + ((1.0f - AALPHA) / 49.0f) * acc_v;
    }
#undef CONSUME

    // block reduction -> per-block partial
    #pragma unroll
    for (int off = 16; off; off >>= 1)
        acc += __shfl_down_sync(0xffffffffu, acc, off);
    if ((t & 31) == 0) red[t >> 5] = acc;
    __syncthreads();
    if (t < 8) {
        float v = red[t];
        #pragma unroll
        for (int off = 4; off; off >>= 1)
            v += __shfl_down_sync(0xffu, v, off);
        if (t == 0) g_part[img * BPI + blockIdx.x] = v;
    }
}

// ---------------------------------------------------------------------------
// reduce partials; weights[b,s] = 0.5*(score/(sum+1e-6) + softmax(lw)[s])
// ---------------------------------------------------------------------------
__global__ void weights_kernel(const float* __restrict__ lw) {
    __shared__ float ss[NIMG];
    __shared__ float soft[3];
    int tid = threadIdx.x;
    if (tid < NIMG) {
        float s = 0.f;
        #pragma unroll
        for (int k = 0; k < BPI; ++k) s += g_part[tid * BPI + k];
        ss[tid] = s;
    }
    if (tid == 0) {
        float a = lw[0], b = lw[1], c = lw[2];
        float m = fmaxf(a, fmaxf(b, c));
        float e0 = expf(a - m), e1 = expf(b - m), e2 = expf(c - m);
        float inv = 1.0f / (e0 + e1 + e2);
        soft[0] = e0 * inv; soft[1] = e1 * inv; soft[2] = e2 * inv;
    }
    __syncthreads();
    if (tid < NIMG) {
        int b = tid / 3;
        int s = tid - b * 3;
        float denom = ss[b * 3] + ss[b * 3 + 1] + ss[b * 3 + 2] + 1e-6f;
        g_weights[tid] = (ss[tid] / denom + soft[s]) * 0.5f;
    }
}

// ---------------------------------------------------------------------------
// fused[b,p] = sum_s logits[b,s,p] * w[b,s]   (float4 vectorized)
// ---------------------------------------------------------------------------
__global__ __launch_bounds__(256) void fuse_kernel(const float* __restrict__ logits,
                                                   float* __restrict__ out) {
    const int N = IMG_H * IMG_W;
    int b = blockIdx.y;
    int i = blockIdx.x * blockDim.x + threadIdx.x;   // over N/4
    float w0 = g_weights[b * 3 + 0];
    float w1 = g_weights[b * 3 + 1];
    float w2 = g_weights[b * 3 + 2];
    const float4* p0 = (const float4*)(logits + (size_t)(b * 3 + 0) * N);
    const float4* p1 = (const float4*)(logits + (size_t)(b * 3 + 1) * N);
    const float4* p2 = (const float4*)(logits + (size_t)(b * 3 + 2) * N);
    float4 a = p0[i], bb = p1[i], cc = p2[i];
    float4 o;
    o.x = a.x * w0 + bb.x * w1 + cc.x * w2;
    o.y = a.y * w0 + bb.y * w1 + cc.y * w2;
    o.z = a.z * w0 + bb.z * w1 + cc.z * w2;
    o.w = a.w * w0 + bb.w * w1 + cc.w * w2;
    ((float4*)out)[(size_t)b * (N / 4) + i] = o;
}

extern "C" void kernel_launch(void* const* d_in, const int* in_sizes, int n_in,
                              void* d_out, int out_size) {
    const float* logits = (const float*)d_in[0];   // (16,3,1024,1024) fp32
    const float* lw     = (const float*)d_in[1];   // (3,) fp32
    float* out          = (float*)d_out;           // (16,1024,1024) fp32

    score_kernel<<<dim3(BPI, NIMG), 256>>>(logits);
    weights_kernel<<<1, 64>>>(lw);
    fuse_kernel<<<dim3((IMG_H * IMG_W / 4) / 256, 16), 256>>>(logits, out);
}

// round 10
// speedup vs baseline: 1.6378x; 1.0011x over previous
#include <cuda_runtime.h>

#define AALPHA 0.42f
#define IMG_H 1024
#define IMG_W 1024
#define NIMG 48     // 16 batches * 3 masks
#define RPB 64      // output rows per block
#define BPI 16      // blocks per image (IMG_H / RPB)

__device__ float g_part[NIMG * BPI];
__device__ float g_weights[NIMG];

// sigmoid(x) = 0.5*tanh(x/2)+0.5  (1 MUFU + 2 fma)
__device__ __forceinline__ float fsig(float x) {
    float t;
    asm("tanh.approx.f32 %0, %1;" : "=f"(t) : "f"(0.5f * x));
    return fmaf(0.5f, t, 0.5f);
}
__device__ __forceinline__ float fsqrt_fast(float x) {
    float r; asm("sqrt.approx.f32 %0, %1;" : "=f"(r) : "f"(x)); return r;
}

// ---------------------------------------------------------------------------
// score = ALPHA * sum(edge) + (1-ALPHA)/49 * sum( cnt(p) * (m_p - mean_p)^2 )
// Software-pipelined smem exchange: at pair-iteration p, LDS halos of pair
// p-1 are issued BEFORE the barrier (data stored before the previous
// barrier), sigmoid+STS of pair p before the barrier, then the barrier, then
// consumption of pair p-1 from pre-barrier registers. The barrier has no
// immediate dependents; LDS latency is covered by sigmoid/STS/BAR.
// ---------------------------------------------------------------------------
__global__ __launch_bounds__(256, 2) void score_kernel(const float* __restrict__ logits) {
    __shared__ float rowbuf[4][1032];   // cols -4..1027, data at offset 4
    __shared__ float red[8];

    const int img = blockIdx.y;
    const int y0  = blockIdx.x * RPB;
    const int t   = threadIdx.x;
    const int c0  = t * 4;
    const float* base = logits + (size_t)img * (IMG_H * IMG_W);

    // zero pad columns of all four buffers (written once)
    if (t < 32) {
        int b = t >> 3, j = t & 7;
        rowbuf[b][(j < 4) ? j : (1020 + j)] = 0.0f;
    }

    float hr[8][4];                      // horizontal-7-sum ring
    float rs[4][4], rt[4][4], rc[4][4];  // conv combo ring
    float vs[4] = {0.f, 0.f, 0.f, 0.f};
    #pragma unroll
    for (int k = 0; k < 8; ++k) { hr[k][0]=hr[k][1]=hr[k][2]=hr[k][3]=0.f; }
    #pragma unroll
    for (int k = 0; k < 4; ++k) {
        #pragma unroll
        for (int j = 0; j < 4; ++j) { rs[k][j]=0.f; rt[k][j]=0.f; rc[k][j]=0.f; }
    }

    float acc;

// consume one row from registers A,B,C (LDS'd pre-barrier). U static.
#define CONS_ROW(U, A, B, C, DOOUT, ACCV, ACCE, ACCL)                       \
    do {                                                                    \
        float h0 = ((A.y + A.z) + (A.w + B.x)) + ((B.y + B.z) + B.w);       \
        float h1 = h0 + C.x - A.y;                                          \
        float h2 = h1 + C.y - A.z;                                          \
        float h3 = h2 + C.z - A.w;                                          \
        vs[0] += h0 - hr[((U) + 1) & 7][0];                                 \
        vs[1] += h1 - hr[((U) + 1) & 7][1];                                 \
        vs[2] += h2 - hr[((U) + 1) & 7][2];                                 \
        vs[3] += h3 - hr[((U) + 1) & 7][3];                                 \
        hr[(U) & 7][0] = h0; hr[(U) & 7][1] = h1;                           \
        hr[(U) & 7][2] = h2; hr[(U) & 7][3] = h3;                           \
        if (DOOUT) {                                                        \
            const int T = (U) & 3, M = ((U) + 1) & 3, Bo = ((U) + 2) & 3;   \
            _Pragma("unroll")                                               \
            for (int j = 0; j < 4; ++j) {                                   \
                float gxv = fmaf(2.f, rt[M][j], rt[T][j] + rt[Bo][j]);      \
                float gyv = rs[T][j] - rs[Bo][j];                           \
                float lap = fmaf(-6.f, rc[M][j],                            \
                                 (rc[T][j] + rc[Bo][j]) + rs[M][j]);        \
                ACCE += fsqrt_fast(fmaf(gxv, gxv, gyv * gyv));              \
                ACCL += fabsf(lap);                                         \
                float d = fmaf(-(1.f / 49.f), vs[j], rc[M][j]);             \
                (ACCV)[j] = fmaf(d, d, (ACCV)[j]);                          \
            }                                                               \
        }                                                                   \
        const int W = (U) & 3;                                              \
        rs[W][0] = fmaf(2.f, B.x, A.w + B.y); rt[W][0] = A.w - B.y; rc[W][0] = B.x; \
        rs[W][1] = fmaf(2.f, B.y, B.x + B.z); rt[W][1] = B.x - B.z; rc[W][1] = B.y; \
        rs[W][2] = fmaf(2.f, B.z, B.y + B.w); rt[W][2] = B.y - B.w; rc[W][2] = B.z; \
        rs[W][3] = fmaf(2.f, B.w, B.z + C.x); rt[W][3] = B.z - C.x; rc[W][3] = B.w; \
    } while (0)

    if (blockIdx.x >= 1 && blockIdx.x <= 14) {
        // ================= clean path: all rows in-bounds, chf = 7 =========
        float accv[4] = {0.f, 0.f, 0.f, 0.f};
        float acc_e = 0.f, acc_l = 0.f;

        const float* rp = base + (size_t)(y0 - 3) * IMG_W + c0;
        float4 cur0 = *(const float4*)rp;
        float4 cur1 = *(const float4*)(rp + IMG_W);
        rp += 2 * IMG_W;

// pair-iteration: consume rows UC,UC+1 from buf-pair BC (LDS before BAR),
// store current pair into buf-pair BS, prefetch next pair. All flags static.
#define PAIRX(UC, BS, BC, DOCONS, DOOUT, DOSTORE, DOPREF)                   \
    do {                                                                    \
        float4 n0, n1;                                                      \
        if (DOPREF) {                                                       \
            n0 = *(const float4*)rp;                                        \
            n1 = *(const float4*)(rp + IMG_W);                              \
            rp += 2 * IMG_W;                                                \
        }                                                                   \
        float4 A0, B0, C0, A1, B1, C1;                                      \
        if (DOCONS) {                                                       \
            const float* rb0 = rowbuf[2 * (BC)];                            \
            const float* rb1 = rowbuf[2 * (BC) + 1];                        \
            A0 = *(const float4*)(rb0 + c0);                                \
            B0 = *(const float4*)(rb0 + c0 + 4);                            \
            C0 = *(const float4*)(rb0 + c0 + 8);                            \
            A1 = *(const float4*)(rb1 + c0);                                \
            B1 = *(const float4*)(rb1 + c0 + 4);                            \
            C1 = *(const float4*)(rb1 + c0 + 8);                            \
        }                                                                   \
        if (DOSTORE) {                                                      \
            float a0 = fsig(cur0.x), a1 = fsig(cur0.y);                     \
            float a2 = fsig(cur0.z), a3 = fsig(cur0.w);                     \
            float b0 = fsig(cur1.x), b1 = fsig(cur1.y);                     \
            float b2 = fsig(cur1.z), b3 = fsig(cur1.w);                     \
            *(float4*)(rowbuf[2 * (BS)] + 4 + c0) =                         \
                make_float4(a0, a1, a2, a3);                                \
            *(float4*)(rowbuf[2 * (BS) + 1] + 4 + c0) =                     \
                make_float4(b0, b1, b2, b3);                                \
        }                                                                   \
        __syncthreads();                                                    \
        if (DOCONS) {                                                       \
            CONS_ROW((UC),     A0, B0, C0, DOOUT, accv, acc_e, acc_l);      \
            CONS_ROW((UC) + 1, A1, B1, C1, DOOUT, accv, acc_e, acc_l);      \
        }                                                                   \
        if (DOPREF) { cur0 = n0; cur1 = n1; }                               \
    } while (0)

        // k=0: store rows 0,1; prefetch 2,3; no consume
        PAIRX(0, 0, 0, false, false, true, true);
        // k=1..4: consume rows 0..7 (outputs at 6,7)
        PAIRX(0, 1, 0, true, false, true, true);
        PAIRX(2, 0, 1, true, false, true, true);
        PAIRX(4, 1, 0, true, false, true, true);
        PAIRX(6, 0, 1, true, true,  true, true);
        // k=5..32: consume rows 8..63, all outputs
        for (int ii = 0; ii < 7; ++ii) {
            PAIRX(0, 1, 0, true, true, true, true);
            PAIRX(2, 0, 1, true, true, true, true);
            PAIRX(4, 1, 0, true, true, true, true);
            PAIRX(6, 0, 1, true, true, true, true);
        }
        // k=33: consume 64,65; store 66,67; prefetch 68,69
        PAIRX(0, 1, 0, true, true, true, true);
        // k=34: consume 66,67; store 68,69; no prefetch
        PAIRX(2, 0, 1, true, true, true, false);
        // k=35: drain — consume 68,69 only
        PAIRX(4, 1, 0, true, true, false, false);
#undef PAIRX

        // fold cw/7 per column and 0.5*|lap| at the end
        float acc_v_tot = 0.f;
        #pragma unroll
        for (int j = 0; j < 4; ++j) {
            int col = c0 + j;
            float cwn = (float)(min(col, 3) + min(IMG_W - 1 - col, 3) + 1) * (1.0f / 7.0f);
            acc_v_tot = fmaf(accv[j], cwn, acc_v_tot);
        }
        float acc_e_tot = fmaf(0.5f, acc_l, acc_e);
        acc = AALPHA * acc_e_tot + ((1.0f - AALPHA) / 49.0f) * 7.0f * acc_v_tot;
    } else {
        // ================= guarded path (blocks 0 and 15), per-row =========
        float acc_e = 0.f, acc_l = 0.f, acc_v = 0.f;
        float cwf[4];
        #pragma unroll
        for (int j = 0; j < 4; ++j) {
            int col = c0 + j;
            cwf[j] = (float)(min(col, 3) + min(IMG_W - 1 - col, 3) + 1);
        }

        float4 cur = make_float4(0.f, 0.f, 0.f, 0.f);
        {
            int gy = y0 - 3;
            if ((unsigned)gy < IMG_H)
                cur = *(const float4*)(base + (size_t)gy * IMG_W + c0);
        }
        for (int ii = 0; ii < 72; ii += 8) {
            #pragma unroll
            for (int u = 0; u < 8; ++u) {
                const int i  = ii + u;
                const int gy = y0 - 3 + i;
                const bool valid = ((unsigned)gy < IMG_H) && (i < 70);

                float4 nxt = make_float4(0.f, 0.f, 0.f, 0.f);
                {
                    int gyn = gy + 1;
                    if ((unsigned)gyn < IMG_H && (i + 1) < 70)
                        nxt = *(const float4*)(base + (size_t)gyn * IMG_W + c0);
                }
                float m0 = valid ? fsig(cur.x) : 0.f;
                float m1 = valid ? fsig(cur.y) : 0.f;
                float m2 = valid ? fsig(cur.z) : 0.f;
                float m3 = valid ? fsig(cur.w) : 0.f;
                float* rb = rowbuf[u & 1];
                *(float4*)(rb + 4 + c0) = make_float4(m0, m1, m2, m3);
                __syncthreads();

                const float4 A = *(const float4*)(rb + c0);
                const float4 C = *(const float4*)(rb + c0 + 8);

                float h0 = ((A.y + A.z) + (A.w + m0)) + ((m1 + m2) + m3);
                float h1 = h0 + C.x - A.y;
                float h2 = h1 + C.y - A.z;
                float h3 = h2 + C.z - A.w;

                vs[0] += h0 - hr[(u + 1) & 7][0];
                vs[1] += h1 - hr[(u + 1) & 7][1];
                vs[2] += h2 - hr[(u + 1) & 7][2];
                vs[3] += h3 - hr[(u + 1) & 7][3];
                hr[u][0] = h0; hr[u][1] = h1; hr[u][2] = h2; hr[u][3] = h3;

                if (i >= 6 && i < 70) {
                    const int yo = gy - 3;
                    const float chf = (float)(min(yo, 3) + min(IMG_H - 1 - yo, 3) + 1);
                    const int T = u & 3, M = (u + 1) & 3, Bo = (u + 2) & 3;
                    float rowv = 0.f;
                    #pragma unroll
                    for (int j = 0; j < 4; ++j) {
                        float gxv = fmaf(2.f, rt[M][j], rt[T][j] + rt[Bo][j]);
                        float gyv = rs[T][j] - rs[Bo][j];
                        float lap = fmaf(-6.f, rc[M][j], (rc[T][j] + rc[Bo][j]) + rs[M][j]);
                        acc_e += fsqrt_fast(fmaf(gxv, gxv, gyv * gyv));
                        acc_l += fabsf(lap);
                        float d = fmaf(-(1.f / 49.f), vs[j], rc[M][j]);
                        rowv = fmaf(d * cwf[j], d, rowv);
                    }
                    acc_v += chf * rowv;
                }

                const int W = u & 3;
                rs[W][0] = fmaf(2.f, m0, A.w + m1); rt[W][0] = A.w - m1; rc[W][0] = m0;
                rs[W][1] = fmaf(2.f, m1, m0 + m2);  rt[W][1] = m0 - m2;  rc[W][1] = m1;
                rs[W][2] = fmaf(2.f, m2, m1 + m3);  rt[W][2] = m1 - m3;  rc[W][2] = m2;
                rs[W][3] = fmaf(2.f, m3, m2 + C.x); rt[W][3] = m2 - C.x; rc[W][3] = m3;

                cur = nxt;
            }
        }
        float acc_e_tot = fmaf(0.5f, acc_l, acc_e);
        acc = AALPHA * acc_e_tot + ((1.0f - AALPHA) / 49.0f) * acc_v;
    }
#undef CONS_ROW

    // block reduction -> per-block partial
    #pragma unroll
    for (int off = 16; off; off >>= 1)
        acc += __shfl_down_sync(0xffffffffu, acc, off);
    if ((t & 31) == 0) red[t >> 5] = acc;
    __syncthreads();
    if (t < 8) {
        float v = red[t];
        #pragma unroll
        for (int off = 4; off; off >>= 1)
            v += __shfl_down_sync(0xffu, v, off);
        if (t == 0) g_part[img * BPI + blockIdx.x] = v;
    }
}

// ---------------------------------------------------------------------------
// reduce partials; weights[b,s] = 0.5*(score/(sum+1e-6) + softmax(lw)[s])
// ---------------------------------------------------------------------------
__global__ void weights_kernel(const float* __restrict__ lw) {
    __shared__ float ss[NIMG];
    __shared__ float soft[3];
    int tid = threadIdx.x;
    if (tid < NIMG) {
        float s = 0.f;
        #pragma unroll
        for (int k = 0; k < BPI; ++k) s += g_part[tid * BPI + k];
        ss[tid] = s;
    }
    if (tid == 0) {
        float a = lw[0], b = lw[1], c = lw[2];
        float m = fmaxf(a, fmaxf(b, c));
        float e0 = expf(a - m), e1 = expf(b - m), e2 = expf(c - m);
        float inv = 1.0f / (e0 + e1 + e2);
        soft[0] = e0 * inv; soft[1] = e1 * inv; soft[2] = e2 * inv;
    }
    __syncthreads();
    if (tid < NIMG) {
        int b = tid / 3;
        int s = tid - b * 3;
        float denom = ss[b * 3] + ss[b * 3 + 1] + ss[b * 3 + 2] + 1e-6f;
        g_weights[tid] = (ss[tid] / denom + soft[s]) * 0.5f;
    }
}

// ---------------------------------------------------------------------------
// fused[b,p] = sum_s logits[b,s,p] * w[b,s]   (float4 vectorized)
// ---------------------------------------------------------------------------
__global__ __launch_bounds__(256) void fuse_kernel(const float* __restrict__ logits,
                                                   float* __restrict__ out) {
    const int N = IMG_H * IMG_W;
    int b = blockIdx.y;
    int i = blockIdx.x * blockDim.x + threadIdx.x;   // over N/4
    float w0 = g_weights[b * 3 + 0];
    float w1 = g_weights[b * 3 + 1];
    float w2 = g_weights[b * 3 + 2];
    const float4* p0 = (const float4*)(logits + (size_t)(b * 3 + 0) * N);
    const float4* p1 = (const float4*)(logits + (size_t)(b * 3 + 1) * N);
    const float4* p2 = (const float4*)(logits + (size_t)(b * 3 + 2) * N);
    float4 a = p0[i], bb = p1[i], cc = p2[i];
    float4 o;
    o.x = a.x * w0 + bb.x * w1 + cc.x * w2;
    o.y = a.y * w0 + bb.y * w1 + cc.y * w2;
    o.z = a.z * w0 + bb.z * w1 + cc.z * w2;
    o.w = a.w * w0 + bb.w * w1 + cc.w * w2;
    ((float4*)out)[(size_t)b * (N / 4) + i] = o;
}

extern "C" void kernel_launch(void* const* d_in, const int* in_sizes, int n_in,
                              void* d_out, int out_size) {
    const float* logits = (const float*)d_in[0];   // (16,3,1024,1024) fp32
    const float* lw     = (const float*)d_in[1];   // (3,) fp32
    float* out          = (float*)d_out;           // (16,1024,1024) fp32

    score_kernel<<<dim3(BPI, NIMG), 256>>>(logits);
    weights_kernel<<<1, 64>>>(lw);
    fuse_kernel<<<dim3((IMG_H * IMG_W / 4) / 256, 16), 256>>>(logits, out);
}